// round 3
// baseline (speedup 1.0000x reference)
#include <cuda_runtime.h>
#include <cstdint>

#define TILE_N 32
#define THREADS 256
#define XS 1028           // x_s row stride (words): 1024+4, ≡4 mod 32 -> conflict-free frag loads
#define ZS 68             // z_s row stride
#define WS 68             // w_s row stride
#define OSTMAX (64*7+4)   // out-stage max row stride (lo=3)

static_assert(OSTMAX == 452, "");

__device__ __forceinline__ unsigned f2tf(float f) {
    unsigned u; asm("cvt.rna.tf32.f32 %0, %1;" : "=r"(u) : "f"(f)); return u;
}

__global__ __launch_bounds__(THREADS, 1)
void tp_kernel(const float* __restrict__ x, const float* __restrict__ W,
               const float* __restrict__ hzero, const float* __restrict__ hpos,
               const float* __restrict__ hneg, float* __restrict__ out)
{
    extern __shared__ float smem[];
    float*    x_s = smem;                                  // TILE_N * XS
    unsigned* z_s = (unsigned*)(smem + TILE_N * XS);       // TILE_N * ZS (tf32 bits)
    unsigned* w_s = z_s + TILE_N * ZS;                     // 64 * WS (tf32 bits)
    float*    o_s = (float*)(w_s + 64 * WS);               // TILE_N * OSTMAX

    const int tid = threadIdx.x;
    const long long n0 = (long long)blockIdx.x * TILE_N;

    // ---- load x tile: 32 rows x 1024 floats, coalesced float4 ----
    {
        const float4* xg = (const float4*)(x + n0 * 1024);
        #pragma unroll 4
        for (int q = tid; q < TILE_N * 256; q += THREADS) {
            int r = q >> 8, c = q & 255;
            float4 v = xg[r * 256 + c];
            float* d = x_s + r * XS + (c << 2);
            d[0] = v.x; d[1] = v.y; d[2] = v.z; d[3] = v.w;
        }
    }
    __syncthreads();

    const int warp = tid >> 5, lane = tid & 31;
    const int wm = warp >> 2, wn = warp & 3;     // warp grid: 2 (M) x 4 (N)
    const int g  = lane >> 2, t4 = lane & 3;
    const int r0 = wm * 16 + g;                  // fragment base row

    for (int oi = 0; oi < 4; ++oi) {
        const int lo = oi, so = 2 * oi + 1;
        const int offo = 64 * oi * oi;           // {0,64,256,576}
        const int ost = 64 * so + 4;

        for (int q = tid; q < TILE_N * ost; q += THREADS) o_s[q] = 0.f;
        // (zero -> first accumulate is separated by the syncs below)

        for (int ii = 0; ii < 4; ++ii) {
            const int li = ii, si = 2 * ii + 1;
            const int base = 64 * ii * ii;       // {0,64,256,576}
            const int p = (oi << 2) + ii;

            __syncthreads();                      // everyone done reading previous w_s
            {   // stage W_p[64][64] as tf32 (B operand: B[k=i][n=o] = W[o][i] -> row-major W works)
                const float* Wg = W + p * 4096;
                #pragma unroll 4
                for (int q = tid; q < 4096; q += THREADS)
                    w_s[(q >> 6) * WS + (q & 63)] = f2tf(Wg[q]);
            }

            const int mmax = (lo < li) ? lo : li;
            const float h0 = __ldg(hzero + p);

            for (int m = 0; m <= mmax; ++m) {
                float hp = 0.f, hn = 0.f;
                if (m > 0) { hp = __ldg(hpos + p * 3 + m - 1); hn = __ldg(hneg + p * 3 + m - 1); }
                const int nv = (m == 0) ? 1 : 2;

                for (int v = 0; v < nv; ++v) {
                    __syncthreads();  // prev mma done with z_s; also orders w_s stores on first pass
                    // ---- build z[32][64] with h-coeffs folded (44-vgemm form) ----
                    for (int e = tid; e < TILE_N * 64; e += THREADS) {
                        int r = e >> 6, i = e & 63;
                        const float* xr = x_s + r * XS + base + i * si;
                        float zz;
                        if (m == 0)      zz = h0 * xr[li];
                        else if (v == 0) zz = hp * xr[li + m] + hn * xr[li - m];
                        else             zz = hp * xr[li - m] - hn * xr[li + m];
                        z_s[r * ZS + i] = f2tf(zz);
                    }
                    __syncthreads();

                    const int oc = (m == 0) ? lo : ((v == 0) ? lo + m : lo - m);

                    // ---- 32x64 += z(32x64) @ W^T via mma.m16n8k4.tf32, K=64 ----
                    float acc[2][4];
                    #pragma unroll
                    for (int nt = 0; nt < 2; ++nt)
                        acc[nt][0] = acc[nt][1] = acc[nt][2] = acc[nt][3] = 0.f;

                    const unsigned* za = z_s + r0 * ZS + t4;
                    const unsigned* zb = z_s + (r0 + 8) * ZS + t4;
                    const unsigned* w0 = w_s + (wn * 16 + g) * WS + t4;
                    const unsigned* w1 = w0 + 8 * WS;
                    #pragma unroll
                    for (int s = 0; s < 16; ++s) {
                        unsigned a0 = za[4 * s], a1 = zb[4 * s];
                        unsigned b0 = w0[4 * s], b1 = w1[4 * s];
                        asm volatile("mma.sync.aligned.m16n8k4.row.col.f32.tf32.tf32.f32 "
                            "{%0,%1,%2,%3}, {%4,%5}, {%6}, {%0,%1,%2,%3};"
                            : "+f"(acc[0][0]), "+f"(acc[0][1]), "+f"(acc[0][2]), "+f"(acc[0][3])
                            : "r"(a0), "r"(a1), "r"(b0));
                        asm volatile("mma.sync.aligned.m16n8k4.row.col.f32.tf32.tf32.f32 "
                            "{%0,%1,%2,%3}, {%4,%5}, {%6}, {%0,%1,%2,%3};"
                            : "+f"(acc[1][0]), "+f"(acc[1][1]), "+f"(acc[1][2]), "+f"(acc[1][3])
                            : "r"(a0), "r"(a1), "r"(b1));
                    }

                    // ---- accumulate into interleaved-channel out stage ----
                    #pragma unroll
                    for (int nt = 0; nt < 2; ++nt) {
                        int o0 = wn * 16 + nt * 8 + 2 * t4;
                        float* d0 = o_s + r0 * ost + o0 * so + oc;
                        float* d1 = o_s + (r0 + 8) * ost + o0 * so + oc;
                        d0[0]  += acc[nt][0];
                        d0[so] += acc[nt][1];
                        d1[0]  += acc[nt][2];
                        d1[so] += acc[nt][3];
                    }
                }
            }
        }
        __syncthreads();
        // ---- epilogue: contiguous float4 stores of this output block ----
        {
            const int nf4 = 16 * so;  // float4 per row
            for (int q = tid; q < TILE_N * nf4; q += THREADS) {
                int r = q / nf4, c = q - r * nf4;
                float4 v = *(const float4*)(o_s + r * ost + (c << 2));
                *(float4*)(out + (n0 + r) * 1024 + offo + (c << 2)) = v;
            }
        }
        __syncthreads();
    }
}

extern "C" void kernel_launch(void* const* d_in, const int* in_sizes, int n_in,
                              void* d_out, int out_size) {
    const float* x  = (const float*)d_in[0];
    const float* w  = (const float*)d_in[1];
    const float* hz = (const float*)d_in[2];
    const float* hp = (const float*)d_in[3];
    const float* hn = (const float*)d_in[4];
    float* out = (float*)d_out;

    const int n = in_sizes[0] / 1024;             // 65536
    const int grid = n / TILE_N;                  // 2048
    const int smem_bytes = (TILE_N * XS + TILE_N * ZS + 64 * WS + TILE_N * OSTMAX) * 4; // 215552 B

    cudaFuncSetAttribute(tp_kernel, cudaFuncAttributeMaxDynamicSharedMemorySize, smem_bytes);
    tp_kernel<<<grid, THREADS, smem_bytes>>>(x, w, hz, hp, hn, out);
}

// round 5
// speedup vs baseline: 3.1001x; 3.1001x over previous
#include <cuda_runtime.h>
#include <cstdint>

#define TILE_N 32
#define THREADS 256
#define XS 1028            // x_s row stride (words) ≡ 4 (mod 32): conflict-free frag reads
#define WS 68              // w_s row stride ≡ 4 (mod 32)
#define OST_MAX 452        // out-stage row stride for lo=3 (64*7+4)

__device__ __forceinline__ unsigned f2tf(float f) {
    unsigned u; asm("cvt.rna.tf32.f32 %0, %1;" : "=r"(u) : "f"(f)); return u;
}

#define MMA8(C, A0, A1, A2, A3, B0, B1)                                        \
    asm volatile("mma.sync.aligned.m16n8k8.row.col.f32.tf32.tf32.f32 "         \
        "{%0,%1,%2,%3}, {%4,%5,%6,%7}, {%8,%9}, {%0,%1,%2,%3};"                \
        : "+f"((C)[0]), "+f"((C)[1]), "+f"((C)[2]), "+f"((C)[3])               \
        : "r"(A0), "r"(A1), "r"(A2), "r"(A3), "r"(B0), "r"(B1))

__global__ __launch_bounds__(THREADS, 1)
void tp_kernel(const float* __restrict__ x, const float* __restrict__ W,
               const float* __restrict__ hzero, const float* __restrict__ hpos,
               const float* __restrict__ hneg, float* __restrict__ out)
{
    extern __shared__ float smem[];
    float*    x_s = smem;                              // TILE_N * XS
    unsigned* w_s = (unsigned*)(smem + TILE_N * XS);   // 64 * WS (tf32 bits)
    float*    o_s = (float*)(w_s + 64 * WS);           // TILE_N * OST_MAX

    const int tid = threadIdx.x;
    const long long n0 = (long long)blockIdx.x * TILE_N;

    // ---- load x tile: 32 rows x 1024 floats, coalesced float4 ----
    {
        const float4* xg = (const float4*)(x + n0 * 1024);
        #pragma unroll 4
        for (int q = tid; q < TILE_N * 256; q += THREADS) {
            int r = q >> 8, c = q & 255;
            float4 v = xg[r * 256 + c];
            float* d = x_s + r * XS + (c << 2);
            d[0] = v.x; d[1] = v.y; d[2] = v.z; d[3] = v.w;
        }
    }
    __syncthreads();

    const int warp = tid >> 5, lane = tid & 31;
    const int wm = warp >> 2, wn = warp & 3;       // 2 (M) x 4 (N) warp grid
    const int g  = lane >> 2, t4 = lane & 3;
    const int r0 = wm * 16 + g;
    const float* xrow0 = x_s + r0 * XS;
    const float* xrow1 = xrow0 + 8 * XS;

    #pragma unroll
    for (int oi = 0; oi < 4; ++oi) {
        const int lo = oi, so = 2 * oi + 1;
        const int offo = 64 * oi * oi;
        const int ost = 64 * so + 4;

        // register accumulators for all so output channels of this block
        float acc[2][7][4];
        #pragma unroll
        for (int nt = 0; nt < 2; ++nt)
            #pragma unroll
            for (int co = 0; co <= 2 * oi; ++co) {
                acc[nt][co][0] = 0.f; acc[nt][co][1] = 0.f;
                acc[nt][co][2] = 0.f; acc[nt][co][3] = 0.f;
            }

        for (int ii = 0; ii < 4; ++ii) {
            const int li = ii, si = 2 * ii + 1;
            const int base = 64 * ii * ii;
            const int p = (oi << 2) + ii;

            __syncthreads();   // prior path done reading w_s
            {   // stage W_p[64][64] as tf32, vectorized
                const float4* Wg = (const float4*)(W + p * 4096);
                #pragma unroll
                for (int q = tid; q < 1024; q += THREADS) {
                    float4 v = Wg[q];
                    uint4 u = make_uint4(f2tf(v.x), f2tf(v.y), f2tf(v.z), f2tf(v.w));
                    *(uint4*)(w_s + (q >> 4) * WS + ((q & 15) << 2)) = u;
                }
            }
            __syncthreads();

            // ---- cache B (W) fragments in registers: reused by all vgemms of this path ----
            unsigned bw[2][8][2];
            {
                const unsigned* wp = w_s + (wn * 16 + g) * WS + t4;
                #pragma unroll
                for (int nt = 0; nt < 2; ++nt)
                    #pragma unroll
                    for (int s = 0; s < 8; ++s) {
                        bw[nt][s][0] = wp[nt * 8 * WS + 8 * s];
                        bw[nt][s][1] = wp[nt * 8 * WS + 8 * s + 4];
                    }
            }

            const float* xa0 = xrow0 + base + li;
            const float* xa1 = xrow1 + base + li;
            const float h0 = __ldg(hzero + p);

            // ---- m = 0 vgemm: A built on the fly from x_s ----
            #pragma unroll
            for (int s = 0; s < 8; ++s) {
                int c0 = (t4 + 8 * s) * si, c1 = c0 + 4 * si;
                unsigned a0 = f2tf(h0 * xa0[c0]), a1 = f2tf(h0 * xa1[c0]);
                unsigned a2 = f2tf(h0 * xa0[c1]), a3 = f2tf(h0 * xa1[c1]);
                MMA8(acc[0][lo], a0, a1, a2, a3, bw[0][s][0], bw[0][s][1]);
                MMA8(acc[1][lo], a0, a1, a2, a3, bw[1][s][0], bw[1][s][1]);
            }

            // ---- m >= 1: fused (+m, -m) vgemm pair sharing x loads ----
            #pragma unroll
            for (int m = 1; m <= oi; ++m) {          // oi compile-time under unroll
                if (ii >= m) {
                    const float hp = __ldg(hpos + p * 3 + m - 1);
                    const float hn = __ldg(hneg + p * 3 + m - 1);
                    #pragma unroll
                    for (int s = 0; s < 8; ++s) {
                        int c0 = (t4 + 8 * s) * si, c1 = c0 + 4 * si;
                        float xp00 = xa0[c0 + m], xn00 = xa0[c0 - m];
                        float xp10 = xa1[c0 + m], xn10 = xa1[c0 - m];
                        float xp01 = xa0[c1 + m], xn01 = xa0[c1 - m];
                        float xp11 = xa1[c1 + m], xn11 = xa1[c1 - m];
                        unsigned u0 = f2tf(hp * xp00 + hn * xn00);
                        unsigned u1 = f2tf(hp * xp10 + hn * xn10);
                        unsigned u2 = f2tf(hp * xp01 + hn * xn01);
                        unsigned u3 = f2tf(hp * xp11 + hn * xn11);
                        unsigned v0 = f2tf(hp * xn00 - hn * xp00);
                        unsigned v1 = f2tf(hp * xn10 - hn * xp10);
                        unsigned v2 = f2tf(hp * xn01 - hn * xp01);
                        unsigned v3 = f2tf(hp * xn11 - hn * xp11);
                        MMA8(acc[0][lo + m], u0, u1, u2, u3, bw[0][s][0], bw[0][s][1]);
                        MMA8(acc[1][lo + m], u0, u1, u2, u3, bw[1][s][0], bw[1][s][1]);
                        MMA8(acc[0][lo - m], v0, v1, v2, v3, bw[0][s][0], bw[0][s][1]);
                        MMA8(acc[1][lo - m], v0, v1, v2, v3, bw[1][s][0], bw[1][s][1]);
                    }
                }
            }
        }

        // ---- epilogue: regs -> interleaved stage -> coalesced float4 global ----
        __syncthreads();   // prior oi's store loop done with o_s
        #pragma unroll
        for (int nt = 0; nt < 2; ++nt) {
            int o0 = wn * 16 + nt * 8 + 2 * t4;
            #pragma unroll
            for (int co = 0; co <= 2 * oi; ++co) {
                float* d0 = o_s + r0 * ost + o0 * so + co;
                float* d1 = d0 + 8 * ost;
                d0[0]  = acc[nt][co][0];
                d0[so] = acc[nt][co][1];
                d1[0]  = acc[nt][co][2];
                d1[so] = acc[nt][co][3];
            }
        }
        __syncthreads();
        {
            const int nf4 = 16 * so;
            for (int q = tid; q < TILE_N * nf4; q += THREADS) {
                int r = q / nf4, c = q - r * nf4;
                float4 v = *(const float4*)(o_s + r * ost + (c << 2));
                *(float4*)(out + (n0 + r) * 1024 + offo + (c << 2)) = v;
            }
        }
    }
}

extern "C" void kernel_launch(void* const* d_in, const int* in_sizes, int n_in,
                              void* d_out, int out_size) {
    const float* x  = (const float*)d_in[0];
    const float* w  = (const float*)d_in[1];
    const float* hz = (const float*)d_in[2];
    const float* hp = (const float*)d_in[3];
    const float* hn = (const float*)d_in[4];
    float* out = (float*)d_out;

    const int n = in_sizes[0] / 1024;              // 65536
    const int grid = n / TILE_N;                   // 2048
    const int smem_bytes = (TILE_N * XS + 64 * WS + TILE_N * OST_MAX) * 4; // 206848 B

    cudaFuncSetAttribute(tp_kernel, cudaFuncAttributeMaxDynamicSharedMemorySize, smem_bytes);
    tp_kernel<<<grid, THREADS, smem_bytes>>>(x, w, hz, hp, hn, out);
}